// round 12
// baseline (speedup 1.0000x reference)
#include <cuda_runtime.h>
#include <math.h>

#define BB 4
#define CC 32
#define RR 64
#define MM 8
#define SS (RR*RR*RR)          // 262144
#define M16 (2*MM)             // 16

typedef unsigned long long ull;

// -------------------- static scratch --------------------
__device__ float  g_x0[BB*CC*SS];             // 134 MB (single buffer, in-place layers)
__device__ float2 g_A [BB*CC*RR*RR*MM];       // 33.5 MB (w-fwd output; reused as h-inv output F)
__device__ float2 g_B [BB*CC*RR*M16*MM];      // 8.4 MB
__device__ float2 g_C [BB*CC*M16*M16*MM];     // 2.1 MB
__device__ float2 g_D [BB*CC*M16*M16*MM];     // 2.1 MB
__device__ float2 g_E [BB*CC*RR*M16*MM];      // 8.4 MB

// -------------------- helpers --------------------
__device__ __forceinline__ ull pack2(float lo, float hi){
    ull r; asm("mov.b64 %0, {%1, %2};" : "=l"(r) : "f"(lo), "f"(hi)); return r;
}
__device__ __forceinline__ float2 unpack2(ull v){
    float2 r; asm("mov.b64 {%0, %1}, %2;" : "=f"(r.x), "=f"(r.y) : "l"(v)); return r;
}
__device__ __forceinline__ void fma2(ull &acc, ull a, ull b){
    asm("fma.rn.f32x2 %0, %1, %2, %0;" : "+l"(acc) : "l"(a), "l"(b));
}

__device__ __forceinline__ float gelu_f(float x){
    // 0.5*x*(1+tanh(0.79788456*(x + 0.044715*x^3))) with HW tanh
    float u = x * (0.7978845608028654f + 0.0356774081f * x * x);
    float t; asm("tanh.approx.f32 %0, %1;" : "=f"(t) : "f"(u));
    return 0.5f * x * (1.0f + t);
}

// tw[t] = (cos(2*pi*t/64), sin(2*pi*t/64))
#define INIT_TW(tw, tid)                                            \
    if ((tid) < 64) {                                               \
        float s_, c_;                                               \
        sincospif((tid) * (1.0f/32.0f), &s_, &c_);                  \
        (tw)[(tid)] = make_float2(c_, s_);                          \
    }

// packed fwd-DFT tables: twcc[i][k]=(cos(2ik*th),cos((2i+1)k*th)), twss=(-sin,-sin)
#define INIT_TWPK(twcc, twss, tid)                                      \
    {   int i_ = (tid) >> 3, k_ = (tid) & 7;                            \
        float s0_, c0_, s1_, c1_;                                       \
        sincospif((float)(2*i_*k_)     * (1.0f/32.0f), &s0_, &c0_);     \
        sincospif((float)((2*i_+1)*k_) * (1.0f/32.0f), &s1_, &c1_);     \
        (twcc)[i_][k_] = pack2(c0_, c1_);                               \
        (twss)[i_][k_] = pack2(-s0_, -s1_);                             \
    }

// ============ fused fc0 + forward w-DFT.  block=(b,dh) ============
__global__ __launch_bounds__(256) void k_fc0_fw(const float* __restrict__ u,
        const float* __restrict__ w, const float* __restrict__ bias,
        float* __restrict__ x0, float2* __restrict__ A){
    __shared__ float us[3][64];
    __shared__ float ws[3][32];
    __shared__ float bs_[32];
    __shared__ __align__(16) float xs2[32][66];
    __shared__ ull twcc[32][8];
    __shared__ ull twss[32][8];
    int t = threadIdx.x;
    INIT_TWPK(twcc, twss, t);
    if (t < 96) ws[t/32][t%32] = w[t];
    if (t < 32) bs_[t] = bias[t];
    int b = blockIdx.x >> 12, dh = blockIdx.x & 4095;
    if (t < 192){ int j = t >> 6, wd = t & 63;
        us[j][wd] = u[((size_t)b*3 + j)*SS + (size_t)dh*64 + wd]; }
    __syncthreads();
    float* xg = x0 + (size_t)b*32*SS + (size_t)dh*64;
#pragma unroll
    for (int r = 0; r < 8; r++){
        int i = t + 256*r; int c = i >> 6, wd = i & 63;
        float v = bs_[c] + us[0][wd]*ws[0][c] + us[1][wd]*ws[1][c] + us[2][wd]*ws[2][c];
        xs2[c][wd] = v; xg[(size_t)c*SS + wd] = v;
    }
    __syncthreads();
    int c = t >> 3, k = t & 7;
    ull re2 = 0ULL, im2 = 0ULL;
#pragma unroll
    for (int i = 0; i < 32; i++){
        ull v2 = *(const ull*)&xs2[c][2*i];
        fma2(re2, v2, twcc[i][k]);
        fma2(im2, v2, twss[i][k]);
    }
    float2 r = unpack2(re2), q = unpack2(im2);
    A[((size_t)(b*32 + c)*4096 + dh)*8 + k] = make_float2(r.x + r.y, q.x + q.y);
}

// ============ folded forward cDFT along h: A(b,c,d,h64,kw8) -> Bt(b,c,d,kh16,kw8) ============
__global__ __launch_bounds__(128) void k_fwd_h(const float2* __restrict__ A, float2* __restrict__ Bt){
    __shared__ float2 as2[2][64][8];
    __shared__ float2 sf [2][33][8];
    __shared__ float2 dfo[2][31][8];
    __shared__ float2 tw[64];
    int t = threadIdx.x;
    INIT_TW(tw, t);
    int bc = blockIdx.x >> 5;
    int dp = blockIdx.x & 31;
    const float2* src = A + ((size_t)bc*4096 + (size_t)dp*128)*8;
    for (int i = t; i < 1024; i += 128) ((float2*)as2)[i] = src[i];
    __syncthreads();
#pragma unroll
    for (int l = 0; l < 2; l++){
        for (int i = t; i < 264; i += 128){
            int h = i >> 3, kw = i & 7;
            float2 v = as2[l][h][kw];
            if (h > 0 && h < 32){ float2 u2 = as2[l][64-h][kw]; v.x += u2.x; v.y += u2.y; }
            sf[l][h][kw] = v;
        }
        for (int i = t; i < 248; i += 128){
            int h = (i >> 3) + 1, kw = i & 7;
            float2 v = as2[l][h][kw];
            float2 u2 = as2[l][64-h][kw];
            dfo[l][h-1][kw] = make_float2(v.x - u2.x, v.y - u2.y);
        }
    }
    __syncthreads();
    int l = t >> 6, tt = t & 63, k = tt >> 3, kw = tt & 7;
    size_t obase = ((size_t)bc*64 + dp*2 + l)*128 + kw;
    if (k == 0){
        float2 acc = sf[l][0][kw];
        float2 C   = acc;
        float2 S   = make_float2(0.f, 0.f);
        int idx = 0;
#pragma unroll
        for (int h = 1; h <= 32; h++){
            float2 sv = sf[l][h][kw];
            acc.x += sv.x; acc.y += sv.y;
            idx = (idx + 8) & 63;
            float2 cs = tw[idx];
            C.x += sv.x*cs.x; C.y += sv.y*cs.x;
            if (h < 32){ float2 dv = dfo[l][h-1][kw]; S.x += dv.x*cs.y; S.y += dv.y*cs.y; }
        }
        Bt[obase]          = acc;                                   // kh=0
        Bt[obase + 64]     = make_float2(C.x - S.y, C.y + S.x);     // kh=8 (f=-8)
    } else {
        float2 C = sf[l][0][kw], S = make_float2(0.f, 0.f);
        int idx = 0;
#pragma unroll
        for (int h = 1; h <= 32; h++){
            idx = (idx + k) & 63;
            float2 cs = tw[idx];
            float2 sv = sf[l][h][kw];
            C.x += sv.x*cs.x; C.y += sv.y*cs.x;
            if (h < 32){ float2 dv = dfo[l][h-1][kw]; S.x += dv.x*cs.y; S.y += dv.y*cs.y; }
        }
        Bt[obase + (size_t)k*8]      = make_float2(C.x + S.y, C.y - S.x);   // f=+k
        Bt[obase + (size_t)(16-k)*8] = make_float2(C.x - S.y, C.y + S.x);   // f=-k
    }
}

// ============ folded forward cDFT along d: Bt(b,c,d64,kh16,kw8) -> Ct(b,c,kd16,kh16,kw8) ============
__global__ __launch_bounds__(128) void k_fwd_d(const float2* __restrict__ Bt, float2* __restrict__ Ct){
    __shared__ float2 as2[2][64][8];
    __shared__ float2 sf [2][33][8];
    __shared__ float2 dfo[2][31][8];
    __shared__ float2 tw[64];
    int t = threadIdx.x;
    INIT_TW(tw, t);
    int bc  = blockIdx.x >> 3;
    int khp = blockIdx.x & 7;
    for (int i = t; i < 1024; i += 128){
        int l = i >> 9, r = i & 511, d = r >> 3, kw = r & 7;
        as2[l][d][kw] = Bt[(size_t)bc*8192 + (size_t)d*128 + (khp*2 + l)*8 + kw];
    }
    __syncthreads();
#pragma unroll
    for (int l = 0; l < 2; l++){
        for (int i = t; i < 264; i += 128){
            int h = i >> 3, kw = i & 7;
            float2 v = as2[l][h][kw];
            if (h > 0 && h < 32){ float2 u2 = as2[l][64-h][kw]; v.x += u2.x; v.y += u2.y; }
            sf[l][h][kw] = v;
        }
        for (int i = t; i < 248; i += 128){
            int h = (i >> 3) + 1, kw = i & 7;
            float2 v = as2[l][h][kw];
            float2 u2 = as2[l][64-h][kw];
            dfo[l][h-1][kw] = make_float2(v.x - u2.x, v.y - u2.y);
        }
    }
    __syncthreads();
    int l = t >> 6, tt = t & 63, k = tt >> 3, kw = tt & 7;
    int kh = khp*2 + l;
    size_t obase = (size_t)bc*2048 + (size_t)kh*8 + kw;   // + kd*128
    if (k == 0){
        float2 acc = sf[l][0][kw];
        float2 C   = acc;
        float2 S   = make_float2(0.f, 0.f);
        int idx = 0;
#pragma unroll
        for (int h = 1; h <= 32; h++){
            float2 sv = sf[l][h][kw];
            acc.x += sv.x; acc.y += sv.y;
            idx = (idx + 8) & 63;
            float2 cs = tw[idx];
            C.x += sv.x*cs.x; C.y += sv.y*cs.x;
            if (h < 32){ float2 dv = dfo[l][h-1][kw]; S.x += dv.x*cs.y; S.y += dv.y*cs.y; }
        }
        Ct[obase]            = acc;
        Ct[obase + 8*128]    = make_float2(C.x - S.y, C.y + S.x);
    } else {
        float2 C = sf[l][0][kw], S = make_float2(0.f, 0.f);
        int idx = 0;
#pragma unroll
        for (int h = 1; h <= 32; h++){
            idx = (idx + k) & 63;
            float2 cs = tw[idx];
            float2 sv = sf[l][h][kw];
            C.x += sv.x*cs.x; C.y += sv.y*cs.x;
            if (h < 32){ float2 dv = dfo[l][h-1][kw]; S.x += dv.x*cs.y; S.y += dv.y*cs.y; }
        }
        Ct[obase + (size_t)k*128]      = make_float2(C.x + S.y, C.y - S.x);
        Ct[obase + (size_t)(16-k)*128] = make_float2(C.x - S.y, C.y + S.x);
    }
}

// ============ mode mix, b-split: block per (kd,kh,b), 1024 blocks ============
// Sibling blocks (same kd,kh) share weight lines -> L2 dedups; 4x MLP vs R5.
__global__ __launch_bounds__(128) void k_mix(const float2* __restrict__ Ct, const float* __restrict__ spw,
                      float2* __restrict__ Dt){
    __shared__ float2 wch[8][8][32];   // [kw][ic][o]
    __shared__ float2 csh[8][8];       // [ic][kw] for this b
    int t = threadIdx.x;
    int kd = blockIdx.x >> 6;
    int kh = (blockIdx.x >> 2) & 15;
    int bq = blockIdx.x & 3;
    int corner = (kd >> 3) + 2*(kh >> 3);
    int md = kd & 7, mh = kh & 7;
    const float* wbase = spw + (size_t)corner*1048576 + (size_t)(md*8 + mh)*16;
    int o = t & 31, g = t >> 5;        // warp g handles kw {2g, 2g+1}
    int modeoff = kd*128 + kh*8;
    float2 acc0 = make_float2(0,0), acc1 = make_float2(0,0);
    for (int ch = 0; ch < 4; ch++){
        int i0 = ch*8;
        __syncthreads();
        for (int idx = t; idx < 1024; idx += 128){
            int p = idx >> 2, q = idx & 3;
            int ic = p >> 5, oo = p & 31;
            const float4 v = *(const float4*)(wbase + (size_t)((i0 + ic)*32 + oo)*1024 + q*4);
            wch[2*q][ic][oo]   = make_float2(v.x, v.y);
            wch[2*q+1][ic][oo] = make_float2(v.z, v.w);
        }
        if (t < 64){
            int ic = t >> 3, kw = t & 7;
            csh[ic][kw] = Ct[(size_t)(bq*32 + i0 + ic)*2048 + modeoff + kw];
        }
        __syncthreads();
#pragma unroll
        for (int ic = 0; ic < 8; ic++){
            float2 w0 = wch[2*g][ic][o], w1 = wch[2*g+1][ic][o];
            float2 a0 = csh[ic][2*g],    a1 = csh[ic][2*g+1];
            acc0.x += a0.x*w0.x - a0.y*w0.y;
            acc0.y += a0.x*w0.y + a0.y*w0.x;
            acc1.x += a1.x*w1.x - a1.y*w1.y;
            acc1.y += a1.x*w1.y + a1.y*w1.x;
        }
    }
    const float sc = 1.0f / 262144.0f;
    size_t ob = (size_t)(bq*32 + o)*2048 + modeoff + 2*g;
    Dt[ob]     = make_float2(acc0.x*sc, acc0.y*sc);
    Dt[ob + 1] = make_float2(acc1.x*sc, acc1.y*sc);
}

// ============ folded inverse along d: Dt(b,o,kd16,kh16,kw8) -> Et(b,o,d64,kh16,kw8) ============
__global__ __launch_bounds__(128) void k_inv_d(const float2* __restrict__ Dt, float2* __restrict__ Et){
    __shared__ float2 in2[2][16][8];
    __shared__ float2 sfc[2][8][8];
    __shared__ float2 dfc[2][8][8];
    __shared__ float2 tw[64];
    int t = threadIdx.x;
    INIT_TW(tw, t);
    int bo  = blockIdx.x >> 3;
    int khp = blockIdx.x & 7;
    for (int i = t; i < 256; i += 128){
        int l = i >> 7, r = i & 127, kd = r >> 3, kw = r & 7;
        in2[l][kd][kw] = Dt[(size_t)bo*2048 + (size_t)kd*128 + (khp*2 + l)*8 + kw];
    }
    __syncthreads();
    if (t < 112){
        int l = t / 56, r = t % 56, k = (r >> 3) + 1, kw = r & 7;
        float2 a = in2[l][k][kw], bv = in2[l][16-k][kw];
        sfc[l][k][kw] = make_float2(a.x + bv.x, a.y + bv.y);
        dfc[l][k][kw] = make_float2(a.x - bv.x, a.y - bv.y);
    }
    __syncthreads();
    int l = t >> 6, tt = t & 63, db = tt >> 3, kw = tt & 7;
    int kh = khp*2 + l;
    float2 a0  = in2[l][0][kw];
    float2 am8 = in2[l][8][kw];
    size_t obase = (size_t)bo*8192 + (size_t)kh*8 + kw;    // + d*128
    for (int dv = db; dv <= 32; dv += 8){
        if (dv == 0){
            float2 x = make_float2(a0.x + am8.x, a0.y + am8.y);
#pragma unroll
            for (int k = 1; k < 8; k++){ float2 s = sfc[l][k][kw]; x.x += s.x; x.y += s.y; }
            Et[obase] = x;
        } else if (dv == 32){
            float2 x = make_float2(a0.x + am8.x, a0.y + am8.y);
#pragma unroll
            for (int k = 1; k < 8; k++){
                float2 s = sfc[l][k][kw];
                if (k & 1){ x.x -= s.x; x.y -= s.y; } else { x.x += s.x; x.y += s.y; }
            }
            Et[obase + (size_t)32*128] = x;
        } else {
            float2 c8 = tw[(8*dv) & 63];
            float2 U = make_float2(a0.x + am8.x*c8.x, a0.y + am8.y*c8.x);
            float2 W = make_float2(-am8.x*c8.y, -am8.y*c8.y);
            int idx = 0;
#pragma unroll
            for (int k = 1; k < 8; k++){
                idx = (idx + dv) & 63;
                float2 cs = tw[idx];
                float2 s  = sfc[l][k][kw];
                float2 dd = dfc[l][k][kw];
                U.x += s.x*cs.x;  U.y += s.y*cs.x;
                W.x += dd.x*cs.y; W.y += dd.y*cs.y;
            }
            Et[obase + (size_t)dv*128]      = make_float2(U.x - W.y, U.y + W.x);
            Et[obase + (size_t)(64-dv)*128] = make_float2(U.x + W.y, U.y - W.x);
        }
    }
}

// ============ folded inverse along h: Et(b,o,d,kh16,kw8) -> F(b,o,d,h64,kw8) ============
__global__ __launch_bounds__(128) void k_inv_h(const float2* __restrict__ Et, float2* __restrict__ F){
    __shared__ float2 in2[2][16][8];
    __shared__ float2 sfc[2][8][8];
    __shared__ float2 dfc[2][8][8];
    __shared__ float2 tw[64];
    int t = threadIdx.x;
    INIT_TW(tw, t);
    size_t bod0 = (size_t)blockIdx.x * 2;
    for (int i = t; i < 256; i += 128) ((float2*)in2)[i] = Et[bod0*128 + i];
    __syncthreads();
    if (t < 112){
        int l = t / 56, r = t % 56, k = (r >> 3) + 1, kw = r & 7;
        float2 a = in2[l][k][kw], bv = in2[l][16-k][kw];
        sfc[l][k][kw] = make_float2(a.x + bv.x, a.y + bv.y);
        dfc[l][k][kw] = make_float2(a.x - bv.x, a.y - bv.y);
    }
    __syncthreads();
    int l = t >> 6, tt = t & 63, hb = tt >> 3, kw = tt & 7;
    float2 a0  = in2[l][0][kw];
    float2 am8 = in2[l][8][kw];
    size_t obase = (bod0 + l)*512 + kw;                    // + h*8
    for (int hv = hb; hv <= 32; hv += 8){
        if (hv == 0){
            float2 x = make_float2(a0.x + am8.x, a0.y + am8.y);
#pragma unroll
            for (int k = 1; k < 8; k++){ float2 s = sfc[l][k][kw]; x.x += s.x; x.y += s.y; }
            F[obase] = x;
        } else if (hv == 32){
            float2 x = make_float2(a0.x + am8.x, a0.y + am8.y);
#pragma unroll
            for (int k = 1; k < 8; k++){
                float2 s = sfc[l][k][kw];
                if (k & 1){ x.x -= s.x; x.y -= s.y; } else { x.x += s.x; x.y += s.y; }
            }
            F[obase + 32*8] = x;
        } else {
            float2 c8 = tw[(8*hv) & 63];
            float2 U = make_float2(a0.x + am8.x*c8.x, a0.y + am8.y*c8.x);
            float2 W = make_float2(-am8.x*c8.y, -am8.y*c8.y);
            int idx = 0;
#pragma unroll
            for (int k = 1; k < 8; k++){
                idx = (idx + hv) & 63;
                float2 cs = tw[idx];
                float2 s  = sfc[l][k][kw];
                float2 dd = dfc[l][k][kw];
                U.x += s.x*cs.x;  U.y += s.y*cs.x;
                W.x += dd.x*cs.y; W.y += dd.y*cs.y;
            }
            F[obase + (size_t)hv*8]      = make_float2(U.x - W.y, U.y + W.x);
            F[obase + (size_t)(64-hv)*8] = make_float2(U.x + W.y, U.y - W.x);
        }
    }
}

// ==== fused: inv-w + 32x32 pointwise + gelu + NEXT layer forward w-DFT ====
__global__ __launch_bounds__(256) void k_layer(const float2* __restrict__ F,
        const float* __restrict__ xin, const float* __restrict__ wpw,
        const float* __restrict__ bpw, float* __restrict__ xout,
        float2* __restrict__ Anext){
    __shared__ __align__(16) float xs[32][66];
    __shared__ __align__(16) float xs2[32][66];
    __shared__ float2 fs[32][9];
    __shared__ __align__(16) ull wdp[32][32];
    __shared__ float bsm[32];
    __shared__ float2 tw[64];
    __shared__ ull twcc[32][8];
    __shared__ ull twss[32][8];
    int t = threadIdx.x;                      // 256
    INIT_TW(tw, t);
    INIT_TWPK(twcc, twss, t);
    int b = blockIdx.x >> 12, dh = blockIdx.x & 4095;
    { int c = t >> 3, o4 = (t & 7)*4;
#pragma unroll
      for (int j = 0; j < 4; j++){ float wv = wpw[c*32 + o4 + j]; wdp[c][o4+j] = pack2(wv, wv); } }
    if (t < 32) bsm[t] = bpw[t];
    const float* xb = xin + (size_t)b*32*SS + (size_t)dh*64;
    for (int i = t; i < 2048; i += 256){ int c = i >> 6, wd = i & 63; xs[c][wd] = xb[(size_t)c*SS + wd]; }
    const float2* fb = F + ((size_t)b*32*4096 + dh)*8;
    { int o = t >> 3, k = t & 7; fs[o][k] = fb[(size_t)o*32768 + k]; }
    __syncthreads();

    int w2 = (t & 31)*2, ob = (t >> 5)*4;
    float2 c0r[7], c1r[7];
#pragma unroll
    for (int k = 1; k < 8; k++){ int t0 = (k*w2) & 63; c0r[k-1] = tw[t0]; c1r[k-1] = tw[(t0+k) & 63]; }
    ull acc2[4];
#pragma unroll
    for (int oi = 0; oi < 4; oi++){ float bv = bsm[ob+oi]; acc2[oi] = pack2(bv, bv); }
#pragma unroll
    for (int c = 0; c < 32; c++){
        ull xv2 = *(const ull*)&xs[c][w2];
        ulonglong2 wA = *(const ulonglong2*)&wdp[c][ob];
        ulonglong2 wB = *(const ulonglong2*)&wdp[c][ob+2];
        fma2(acc2[0], xv2, wA.x);
        fma2(acc2[1], xv2, wA.y);
        fma2(acc2[2], xv2, wB.x);
        fma2(acc2[3], xv2, wB.y);
    }
    float* orow = xout + (size_t)b*32*SS + (size_t)dh*64;
#pragma unroll
    for (int oi = 0; oi < 4; oi++){
        int o = ob + oi;
        float2 f0 = fs[o][0];
        float i0 = f0.x, i1 = f0.x;           // irfft ignores Im of DC mode
#pragma unroll
        for (int k = 1; k < 8; k++){
            float2 fk = fs[o][k];
            float2 ca = c0r[k-1], cb = c1r[k-1];
            i0 += 2.0f*(fk.x*ca.x - fk.y*ca.y);
            i1 += 2.0f*(fk.x*cb.x - fk.y*cb.y);
        }
        float2 av = unpack2(acc2[oi]);
        float v0 = gelu_f(av.x + i0), v1 = gelu_f(av.y + i1);
        *(float2*)&xs2[o][w2]              = make_float2(v0, v1);
        *(float2*)&orow[(size_t)o*SS + w2] = make_float2(v0, v1);
    }
    __syncthreads();
    { int c = t >> 3, k = t & 7;
      ull re2 = 0ULL, im2 = 0ULL;
#pragma unroll
      for (int i = 0; i < 32; i++){
          ull v2 = *(const ull*)&xs2[c][2*i];
          fma2(re2, v2, twcc[i][k]);
          fma2(im2, v2, twss[i][k]);
      }
      float2 r = unpack2(re2), q = unpack2(im2);
      Anext[((size_t)(b*32 + c)*4096 + dh)*8 + k] = make_float2(r.x + r.y, q.x + q.y);
    }
}

// ==== final layer: inv-w + pointwise (no gelu) + fc1 + gelu + fc2 -> tau ====
__global__ __launch_bounds__(256) void k_final(const float2* __restrict__ F,
        const float* __restrict__ xin, const float* __restrict__ wpw,
        const float* __restrict__ bpw,
        const float* __restrict__ w1, const float* __restrict__ b1,
        const float* __restrict__ w2, const float* __restrict__ b2,
        float* __restrict__ tau){
    __shared__ __align__(16) float xs[32][66];
    __shared__ __align__(16) float xs2[32][66];
    __shared__ float2 fs[32][9];
    __shared__ __align__(16) ull wdp[32][32];
    __shared__ float bsm[32];
    __shared__ float2 tw[64];
    __shared__ __align__(16) float w1s[32][128];
    __shared__ float b1s[128];
    __shared__ ull w2p[64][6];
    __shared__ float b2s[8];
    int t = threadIdx.x;                      // 256
    INIT_TW(tw, t);
    int b = blockIdx.x >> 12, dh = blockIdx.x & 4095;
    { int c = t >> 3, o4 = (t & 7)*4;
#pragma unroll
      for (int j = 0; j < 4; j++){ float wv = wpw[c*32 + o4 + j]; wdp[c][o4+j] = pack2(wv, wv); } }
    if (t < 32) bsm[t] = bpw[t];
    for (int i = t; i < 4096; i += 256) w1s[i >> 7][i & 127] = w1[i];
    if (t < 128) b1s[t] = b1[t];
    for (int i = t; i < 384; i += 256){ int hp = i / 6, j = i - hp*6;
        w2p[hp][j] = pack2(w2[(2*hp)*6 + j], w2[(2*hp+1)*6 + j]); }
    if (t < 6) b2s[t] = b2[t];
    const float* xb = xin + (size_t)b*32*SS + (size_t)dh*64;
    for (int i = t; i < 2048; i += 256){ int c = i >> 6, wd = i & 63; xs[c][wd] = xb[(size_t)c*SS + wd]; }
    const float2* fb = F + ((size_t)b*32*4096 + dh)*8;
    { int o = t >> 3, k = t & 7; fs[o][k] = fb[(size_t)o*32768 + k]; }
    __syncthreads();

    {
        int w2_ = (t & 31)*2, ob = (t >> 5)*4;
        float2 c0r[7], c1r[7];
#pragma unroll
        for (int k = 1; k < 8; k++){ int t0 = (k*w2_) & 63; c0r[k-1] = tw[t0]; c1r[k-1] = tw[(t0+k) & 63]; }
        ull acc2[4];
#pragma unroll
        for (int oi = 0; oi < 4; oi++){ float bv = bsm[ob+oi]; acc2[oi] = pack2(bv, bv); }
#pragma unroll
        for (int c = 0; c < 32; c++){
            ull xv2 = *(const ull*)&xs[c][w2_];
            ulonglong2 wA = *(const ulonglong2*)&wdp[c][ob];
            ulonglong2 wB = *(const ulonglong2*)&wdp[c][ob+2];
            fma2(acc2[0], xv2, wA.x);
            fma2(acc2[1], xv2, wA.y);
            fma2(acc2[2], xv2, wB.x);
            fma2(acc2[3], xv2, wB.y);
        }
#pragma unroll
        for (int oi = 0; oi < 4; oi++){
            int o = ob + oi;
            float2 f0 = fs[o][0];
            float i0 = f0.x, i1 = f0.x;
#pragma unroll
            for (int k = 1; k < 8; k++){
                float2 fk = fs[o][k];
                float2 ca = c0r[k-1], cb = c1r[k-1];
                i0 += 2.0f*(fk.x*ca.x - fk.y*ca.y);
                i1 += 2.0f*(fk.x*cb.x - fk.y*cb.y);
            }
            float2 av = unpack2(acc2[oi]);
            *(float2*)&xs2[o][w2_] = make_float2(av.x + i0, av.y + i1);
        }
    }
    __syncthreads();

    {
        int q = t & 3, wd = t >> 2;
        ull g[16];
#pragma unroll
        for (int hq = 0; hq < 8; hq++){
            int H = 16*hq + 4*q;
            g[2*hq]   = pack2(b1s[H],   b1s[H+1]);
            g[2*hq+1] = pack2(b1s[H+2], b1s[H+3]);
        }
#pragma unroll 4
        for (int c = 0; c < 32; c++){
            float xv = xs2[c][wd];
            ull xvd = pack2(xv, xv);
#pragma unroll
            for (int hq = 0; hq < 8; hq++){
                ulonglong2 wp = *(const ulonglong2*)&w1s[c][16*hq + 4*q];
                fma2(g[2*hq],   xvd, wp.x);
                fma2(g[2*hq+1], xvd, wp.y);
            }
        }
        ull a2[6];
#pragma unroll
        for (int j = 0; j < 6; j++) a2[j] = 0ULL;
#pragma unroll
        for (int hq = 0; hq < 8; hq++){
            float2 g01 = unpack2(g[2*hq]), g23 = unpack2(g[2*hq+1]);
            ull gp0 = pack2(gelu_f(g01.x), gelu_f(g01.y));
            ull gp1 = pack2(gelu_f(g23.x), gelu_f(g23.y));
            int hp = 8*hq + 2*q;
#pragma unroll
            for (int j = 0; j < 6; j++){
                fma2(a2[j], gp0, w2p[hp][j]);
                fma2(a2[j], gp1, w2p[hp+1][j]);
            }
        }
        float* tb = tau + (size_t)b*6*SS + (size_t)dh*64 + wd;
#pragma unroll
        for (int j = 0; j < 6; j++){
            float2 av = unpack2(a2[j]);
            float aj = av.x + av.y;
            aj += __shfl_xor_sync(0xffffffffu, aj, 1);
            aj += __shfl_xor_sync(0xffffffffu, aj, 2);
            if (q == 0) tb[(size_t)j*SS] = aj + b2s[j];
        }
    }
}

// ============ NS hard core stencil + 0.001*tau[:3] ============
__global__ void k_stencil(const float* __restrict__ u, const float* __restrict__ tau,
                          float* __restrict__ du){
    int idx = blockIdx.x * 256 + threadIdx.x;
    int s  = idx & (SS - 1);
    int bi = idx >> 18;
    int b  = bi / 3;
    int i  = bi - b*3;
    int w = s & 63, h = (s >> 6) & 63, d = s >> 12;
    const float* ui = u + (size_t)bi * SS;
    float c0 = ui[s];
    int wp = (w + 1) & 63, wm = (w + 63) & 63;
    int hp = (h + 1) & 63, hm = (h + 63) & 63;
    int dp = (d + 1) & 63, dm = (d + 63) & 63;
    float uwp = ui[(d << 12) + (h << 6) + wp], uwm = ui[(d << 12) + (h << 6) + wm];
    float uhp = ui[(d << 12) + (hp << 6) + w], uhm = ui[(d << 12) + (hm << 6) + w];
    float udp = ui[(dp << 12) + (h << 6) + w], udm = ui[(dm << 12) + (h << 6) + w];
    const float inv2dx = (float)(16.0 / 3.14159265358979323846);
    const float invdx2 = (float)(1024.0 / (3.14159265358979323846*3.14159265358979323846));
    float v0 = u[((size_t)b*3 + 0)*SS + s];
    float v1 = u[((size_t)b*3 + 1)*SS + s];
    float v2 = u[((size_t)b*3 + 2)*SS + s];
    float conv = -(v0*(udp - udm) + v1*(uhp - uhm) + v2*(uwp - uwm)) * inv2dx;
    float lap  = (udp + udm + uhp + uhm + uwp + uwm - 6.0f*c0) * invdx2;
    float tv = tau[((size_t)b*6 + i)*SS + s];
    du[idx] = conv + 0.000185f*lap + 0.001f*tv;
}

// ============ launch ============
extern "C" void kernel_launch(void* const* d_in, const int* in_sizes, int n_in,
                              void* d_out, int out_size){
    const float* u      = (const float*)d_in[0];
    const float* fc0_w  = (const float*)d_in[1];
    const float* fc0_b  = (const float*)d_in[2];
    const float* spec_w = (const float*)d_in[3];
    const float* w_pw   = (const float*)d_in[4];
    const float* b_pw   = (const float*)d_in[5];
    const float* fc1_w  = (const float*)d_in[6];
    const float* fc1_b  = (const float*)d_in[7];
    const float* fc2_w  = (const float*)d_in[8];
    const float* fc2_b  = (const float*)d_in[9];

    float* du  = (float*)d_out;
    float* tau = du + (size_t)BB*3*SS;

    float *x0; float2 *A, *Bt, *Ct, *Dt, *Et;
    cudaGetSymbolAddress((void**)&x0, g_x0);
    cudaGetSymbolAddress((void**)&A,  g_A);
    cudaGetSymbolAddress((void**)&Bt, g_B);
    cudaGetSymbolAddress((void**)&Ct, g_C);
    cudaGetSymbolAddress((void**)&Dt, g_D);
    cudaGetSymbolAddress((void**)&Et, g_E);

    k_fc0_fw<<<16384, 256>>>(u, fc0_w, fc0_b, x0, A);

    for (int l = 0; l < 4; l++){
        k_fwd_h<<<4096, 128>>>(A, Bt);
        k_fwd_d<<<1024, 128>>>(Bt, Ct);
        k_mix  <<<1024, 128>>>(Ct, spec_w + (size_t)l*4*32*32*512*2, Dt);
        k_inv_d<<<1024, 128>>>(Dt, Et);
        k_inv_h<<<4096, 128>>>(Et, A);
        if (l < 3){
            k_layer<<<16384, 256>>>(A, x0, w_pw + (size_t)l*1024, b_pw + (size_t)l*32,
                                    x0, A);
        } else {
            k_final<<<16384, 256>>>(A, x0, w_pw + (size_t)l*1024, b_pw + (size_t)l*32,
                                    fc1_w, fc1_b, fc2_w, fc2_b, tau);
        }
    }

    k_stencil<<<12288, 256>>>(u, tau, du);
}

// round 13
// speedup vs baseline: 1.0168x; 1.0168x over previous
#include <cuda_runtime.h>
#include <math.h>

#define BB 4
#define CC 32
#define RR 64
#define MM 8
#define SS (RR*RR*RR)          // 262144
#define M16 (2*MM)             // 16

typedef unsigned long long ull;

// -------------------- static scratch --------------------
__device__ float  g_x0[BB*CC*SS];             // 134 MB (single buffer, in-place layers)
__device__ float2 g_A [BB*CC*RR*RR*MM];       // 33.5 MB (w-fwd output; reused as h-inv output F)
__device__ float2 g_B [BB*CC*RR*M16*MM];      // 8.4 MB
__device__ float2 g_C [BB*CC*M16*M16*MM];     // 2.1 MB
__device__ float2 g_D [BB*CC*M16*M16*MM];     // 2.1 MB
__device__ float2 g_E [BB*CC*RR*M16*MM];      // 8.4 MB

// -------------------- helpers --------------------
__device__ __forceinline__ ull pack2(float lo, float hi){
    ull r; asm("mov.b64 %0, {%1, %2};" : "=l"(r) : "f"(lo), "f"(hi)); return r;
}
__device__ __forceinline__ float2 unpack2(ull v){
    float2 r; asm("mov.b64 {%0, %1}, %2;" : "=f"(r.x), "=f"(r.y) : "l"(v)); return r;
}
__device__ __forceinline__ void fma2(ull &acc, ull a, ull b){
    asm("fma.rn.f32x2 %0, %1, %2, %0;" : "+l"(acc) : "l"(a), "l"(b));
}

__device__ __forceinline__ float gelu_f(float x){
    // 0.5*x*(1+tanh(0.79788456*(x + 0.044715*x^3))) with HW tanh
    float u = x * (0.7978845608028654f + 0.0356774081f * x * x);
    float t; asm("tanh.approx.f32 %0, %1;" : "=f"(t) : "f"(u));
    return 0.5f * x * (1.0f + t);
}

// tw[t] = (cos(2*pi*t/64), sin(2*pi*t/64))
#define INIT_TW(tw, tid)                                            \
    if ((tid) < 64) {                                               \
        float s_, c_;                                               \
        sincospif((tid) * (1.0f/32.0f), &s_, &c_);                  \
        (tw)[(tid)] = make_float2(c_, s_);                          \
    }

// packed fwd-DFT tables: twcc[i][k]=(cos(2ik*th),cos((2i+1)k*th)), twss=(-sin,-sin)
#define INIT_TWPK(twcc, twss, tid)                                      \
    {   int i_ = (tid) >> 3, k_ = (tid) & 7;                            \
        float s0_, c0_, s1_, c1_;                                       \
        sincospif((float)(2*i_*k_)     * (1.0f/32.0f), &s0_, &c0_);     \
        sincospif((float)((2*i_+1)*k_) * (1.0f/32.0f), &s1_, &c1_);     \
        (twcc)[i_][k_] = pack2(c0_, c1_);                               \
        (twss)[i_][k_] = pack2(-s0_, -s1_);                             \
    }

// ============ fused fc0 + forward w-DFT.  block=(b,dh) ============
__global__ __launch_bounds__(256) void k_fc0_fw(const float* __restrict__ u,
        const float* __restrict__ w, const float* __restrict__ bias,
        float* __restrict__ x0, float2* __restrict__ A){
    __shared__ float us[3][64];
    __shared__ float ws[3][32];
    __shared__ float bs_[32];
    __shared__ __align__(16) float xs2[32][66];
    __shared__ ull twcc[32][8];
    __shared__ ull twss[32][8];
    int t = threadIdx.x;
    INIT_TWPK(twcc, twss, t);
    if (t < 96) ws[t/32][t%32] = w[t];
    if (t < 32) bs_[t] = bias[t];
    int b = blockIdx.x >> 12, dh = blockIdx.x & 4095;
    if (t < 192){ int j = t >> 6, wd = t & 63;
        us[j][wd] = u[((size_t)b*3 + j)*SS + (size_t)dh*64 + wd]; }
    __syncthreads();
    float* xg = x0 + (size_t)b*32*SS + (size_t)dh*64;
#pragma unroll
    for (int r = 0; r < 8; r++){
        int i = t + 256*r; int c = i >> 6, wd = i & 63;
        float v = bs_[c] + us[0][wd]*ws[0][c] + us[1][wd]*ws[1][c] + us[2][wd]*ws[2][c];
        xs2[c][wd] = v; xg[(size_t)c*SS + wd] = v;
    }
    __syncthreads();
    int c = t >> 3, k = t & 7;
    ull re2 = 0ULL, im2 = 0ULL;
#pragma unroll
    for (int i = 0; i < 32; i++){
        ull v2 = *(const ull*)&xs2[c][2*i];
        fma2(re2, v2, twcc[i][k]);
        fma2(im2, v2, twss[i][k]);
    }
    float2 r = unpack2(re2), q = unpack2(im2);
    A[((size_t)(b*32 + c)*4096 + dh)*8 + k] = make_float2(r.x + r.y, q.x + q.y);
}

// ============ folded forward cDFT along h: A(b,c,d,h64,kw8) -> Bt(b,c,d,kh16,kw8) ============
__global__ __launch_bounds__(128) void k_fwd_h(const float2* __restrict__ A, float2* __restrict__ Bt){
    __shared__ float2 as2[2][64][8];
    __shared__ float2 sf [2][33][8];
    __shared__ float2 dfo[2][31][8];
    __shared__ float2 tw[64];
    int t = threadIdx.x;
    INIT_TW(tw, t);
    int bc = blockIdx.x >> 5;
    int dp = blockIdx.x & 31;
    const float2* src = A + ((size_t)bc*4096 + (size_t)dp*128)*8;
    for (int i = t; i < 1024; i += 128) ((float2*)as2)[i] = src[i];
    __syncthreads();
#pragma unroll
    for (int l = 0; l < 2; l++){
        for (int i = t; i < 264; i += 128){
            int h = i >> 3, kw = i & 7;
            float2 v = as2[l][h][kw];
            if (h > 0 && h < 32){ float2 u2 = as2[l][64-h][kw]; v.x += u2.x; v.y += u2.y; }
            sf[l][h][kw] = v;
        }
        for (int i = t; i < 248; i += 128){
            int h = (i >> 3) + 1, kw = i & 7;
            float2 v = as2[l][h][kw];
            float2 u2 = as2[l][64-h][kw];
            dfo[l][h-1][kw] = make_float2(v.x - u2.x, v.y - u2.y);
        }
    }
    __syncthreads();
    int l = t >> 6, tt = t & 63, k = tt >> 3, kw = tt & 7;
    size_t obase = ((size_t)bc*64 + dp*2 + l)*128 + kw;
    if (k == 0){
        float2 acc = sf[l][0][kw];
        float2 C   = acc;
        float2 S   = make_float2(0.f, 0.f);
        int idx = 0;
#pragma unroll
        for (int h = 1; h <= 32; h++){
            float2 sv = sf[l][h][kw];
            acc.x += sv.x; acc.y += sv.y;
            idx = (idx + 8) & 63;
            float2 cs = tw[idx];
            C.x += sv.x*cs.x; C.y += sv.y*cs.x;
            if (h < 32){ float2 dv = dfo[l][h-1][kw]; S.x += dv.x*cs.y; S.y += dv.y*cs.y; }
        }
        Bt[obase]          = acc;                                   // kh=0
        Bt[obase + 64]     = make_float2(C.x - S.y, C.y + S.x);     // kh=8 (f=-8)
    } else {
        float2 C = sf[l][0][kw], S = make_float2(0.f, 0.f);
        int idx = 0;
#pragma unroll
        for (int h = 1; h <= 32; h++){
            idx = (idx + k) & 63;
            float2 cs = tw[idx];
            float2 sv = sf[l][h][kw];
            C.x += sv.x*cs.x; C.y += sv.y*cs.x;
            if (h < 32){ float2 dv = dfo[l][h-1][kw]; S.x += dv.x*cs.y; S.y += dv.y*cs.y; }
        }
        Bt[obase + (size_t)k*8]      = make_float2(C.x + S.y, C.y - S.x);   // f=+k
        Bt[obase + (size_t)(16-k)*8] = make_float2(C.x - S.y, C.y + S.x);   // f=-k
    }
}

// ============ folded forward cDFT along d: Bt(b,c,d64,kh16,kw8) -> Ct(b,c,kd16,kh16,kw8) ============
__global__ __launch_bounds__(128) void k_fwd_d(const float2* __restrict__ Bt, float2* __restrict__ Ct){
    __shared__ float2 as2[2][64][8];
    __shared__ float2 sf [2][33][8];
    __shared__ float2 dfo[2][31][8];
    __shared__ float2 tw[64];
    int t = threadIdx.x;
    INIT_TW(tw, t);
    int bc  = blockIdx.x >> 3;
    int khp = blockIdx.x & 7;
    for (int i = t; i < 1024; i += 128){
        int l = i >> 9, r = i & 511, d = r >> 3, kw = r & 7;
        as2[l][d][kw] = Bt[(size_t)bc*8192 + (size_t)d*128 + (khp*2 + l)*8 + kw];
    }
    __syncthreads();
#pragma unroll
    for (int l = 0; l < 2; l++){
        for (int i = t; i < 264; i += 128){
            int h = i >> 3, kw = i & 7;
            float2 v = as2[l][h][kw];
            if (h > 0 && h < 32){ float2 u2 = as2[l][64-h][kw]; v.x += u2.x; v.y += u2.y; }
            sf[l][h][kw] = v;
        }
        for (int i = t; i < 248; i += 128){
            int h = (i >> 3) + 1, kw = i & 7;
            float2 v = as2[l][h][kw];
            float2 u2 = as2[l][64-h][kw];
            dfo[l][h-1][kw] = make_float2(v.x - u2.x, v.y - u2.y);
        }
    }
    __syncthreads();
    int l = t >> 6, tt = t & 63, k = tt >> 3, kw = tt & 7;
    int kh = khp*2 + l;
    size_t obase = (size_t)bc*2048 + (size_t)kh*8 + kw;   // + kd*128
    if (k == 0){
        float2 acc = sf[l][0][kw];
        float2 C   = acc;
        float2 S   = make_float2(0.f, 0.f);
        int idx = 0;
#pragma unroll
        for (int h = 1; h <= 32; h++){
            float2 sv = sf[l][h][kw];
            acc.x += sv.x; acc.y += sv.y;
            idx = (idx + 8) & 63;
            float2 cs = tw[idx];
            C.x += sv.x*cs.x; C.y += sv.y*cs.x;
            if (h < 32){ float2 dv = dfo[l][h-1][kw]; S.x += dv.x*cs.y; S.y += dv.y*cs.y; }
        }
        Ct[obase]            = acc;
        Ct[obase + 8*128]    = make_float2(C.x - S.y, C.y + S.x);
    } else {
        float2 C = sf[l][0][kw], S = make_float2(0.f, 0.f);
        int idx = 0;
#pragma unroll
        for (int h = 1; h <= 32; h++){
            idx = (idx + k) & 63;
            float2 cs = tw[idx];
            float2 sv = sf[l][h][kw];
            C.x += sv.x*cs.x; C.y += sv.y*cs.x;
            if (h < 32){ float2 dv = dfo[l][h-1][kw]; S.x += dv.x*cs.y; S.y += dv.y*cs.y; }
        }
        Ct[obase + (size_t)k*128]      = make_float2(C.x + S.y, C.y - S.x);
        Ct[obase + (size_t)(16-k)*128] = make_float2(C.x - S.y, C.y + S.x);
    }
}

// ============ mode mix (coalesced weights): block per (kd,kh), 256 blocks ============
__global__ __launch_bounds__(128) void k_mix(const float2* __restrict__ Ct, const float* __restrict__ spw,
                      float2* __restrict__ Dt){
    __shared__ float2 wch[8][8][32];   // [kw][ic][o]
    __shared__ float2 csh[4][8][8];    // [b][ic][kw]
    int t = threadIdx.x;
    int kd = blockIdx.x >> 4, kh = blockIdx.x & 15;
    int corner = (kd >> 3) + 2*(kh >> 3);
    int md = kd & 7, mh = kh & 7;
    const float* wbase = spw + (size_t)corner*1048576 + (size_t)(md*8 + mh)*16;
    int o = t & 31, g = t >> 5;        // warp g handles kw {2g, 2g+1}
    int modeoff = kd*128 + kh*8;
    float2 acc[4][2];
#pragma unroll
    for (int b = 0; b < 4; b++){ acc[b][0] = make_float2(0,0); acc[b][1] = make_float2(0,0); }
    for (int ch = 0; ch < 4; ch++){
        int i0 = ch*8;
        __syncthreads();
        for (int idx = t; idx < 1024; idx += 128){
            int p = idx >> 2, q = idx & 3;
            int ic = p >> 5, oo = p & 31;
            const float4 v = *(const float4*)(wbase + (size_t)((i0 + ic)*32 + oo)*1024 + q*4);
            wch[2*q][ic][oo]   = make_float2(v.x, v.y);
            wch[2*q+1][ic][oo] = make_float2(v.z, v.w);
        }
        for (int idx = t; idx < 256; idx += 128){
            int b = idx >> 6, ic = (idx >> 3) & 7, kw = idx & 7;
            csh[b][ic][kw] = Ct[(size_t)(b*32 + i0 + ic)*2048 + modeoff + kw];
        }
        __syncthreads();
#pragma unroll
        for (int ic = 0; ic < 8; ic++){
            float2 w0 = wch[2*g][ic][o], w1 = wch[2*g+1][ic][o];
#pragma unroll
            for (int b = 0; b < 4; b++){
                float2 a0 = csh[b][ic][2*g], a1 = csh[b][ic][2*g+1];
                acc[b][0].x += a0.x*w0.x - a0.y*w0.y;
                acc[b][0].y += a0.x*w0.y + a0.y*w0.x;
                acc[b][1].x += a1.x*w1.x - a1.y*w1.y;
                acc[b][1].y += a1.x*w1.y + a1.y*w1.x;
            }
        }
    }
    const float sc = 1.0f / 262144.0f;
#pragma unroll
    for (int b = 0; b < 4; b++){
        size_t ob = (size_t)(b*32 + o)*2048 + modeoff + 2*g;
        Dt[ob]     = make_float2(acc[b][0].x*sc, acc[b][0].y*sc);
        Dt[ob + 1] = make_float2(acc[b][1].x*sc, acc[b][1].y*sc);
    }
}

// ============ folded inverse along d: Dt(b,o,kd16,kh16,kw8) -> Et(b,o,d64,kh16,kw8) ============
__global__ __launch_bounds__(128) void k_inv_d(const float2* __restrict__ Dt, float2* __restrict__ Et){
    __shared__ float2 in2[2][16][8];
    __shared__ float2 sfc[2][8][8];
    __shared__ float2 dfc[2][8][8];
    __shared__ float2 tw[64];
    int t = threadIdx.x;
    INIT_TW(tw, t);
    int bo  = blockIdx.x >> 3;
    int khp = blockIdx.x & 7;
    for (int i = t; i < 256; i += 128){
        int l = i >> 7, r = i & 127, kd = r >> 3, kw = r & 7;
        in2[l][kd][kw] = Dt[(size_t)bo*2048 + (size_t)kd*128 + (khp*2 + l)*8 + kw];
    }
    __syncthreads();
    if (t < 112){
        int l = t / 56, r = t % 56, k = (r >> 3) + 1, kw = r & 7;
        float2 a = in2[l][k][kw], bv = in2[l][16-k][kw];
        sfc[l][k][kw] = make_float2(a.x + bv.x, a.y + bv.y);
        dfc[l][k][kw] = make_float2(a.x - bv.x, a.y - bv.y);
    }
    __syncthreads();
    int l = t >> 6, tt = t & 63, db = tt >> 3, kw = tt & 7;
    int kh = khp*2 + l;
    float2 a0  = in2[l][0][kw];
    float2 am8 = in2[l][8][kw];
    size_t obase = (size_t)bo*8192 + (size_t)kh*8 + kw;    // + d*128
    for (int dv = db; dv <= 32; dv += 8){
        if (dv == 0){
            float2 x = make_float2(a0.x + am8.x, a0.y + am8.y);
#pragma unroll
            for (int k = 1; k < 8; k++){ float2 s = sfc[l][k][kw]; x.x += s.x; x.y += s.y; }
            Et[obase] = x;
        } else if (dv == 32){
            float2 x = make_float2(a0.x + am8.x, a0.y + am8.y);
#pragma unroll
            for (int k = 1; k < 8; k++){
                float2 s = sfc[l][k][kw];
                if (k & 1){ x.x -= s.x; x.y -= s.y; } else { x.x += s.x; x.y += s.y; }
            }
            Et[obase + (size_t)32*128] = x;
        } else {
            float2 c8 = tw[(8*dv) & 63];
            float2 U = make_float2(a0.x + am8.x*c8.x, a0.y + am8.y*c8.x);
            float2 W = make_float2(-am8.x*c8.y, -am8.y*c8.y);
            int idx = 0;
#pragma unroll
            for (int k = 1; k < 8; k++){
                idx = (idx + dv) & 63;
                float2 cs = tw[idx];
                float2 s  = sfc[l][k][kw];
                float2 dd = dfc[l][k][kw];
                U.x += s.x*cs.x;  U.y += s.y*cs.x;
                W.x += dd.x*cs.y; W.y += dd.y*cs.y;
            }
            Et[obase + (size_t)dv*128]      = make_float2(U.x - W.y, U.y + W.x);
            Et[obase + (size_t)(64-dv)*128] = make_float2(U.x + W.y, U.y - W.x);
        }
    }
}

// ============ folded inverse along h: Et(b,o,d,kh16,kw8) -> F(b,o,d,h64,kw8) ============
__global__ __launch_bounds__(128) void k_inv_h(const float2* __restrict__ Et, float2* __restrict__ F){
    __shared__ float2 in2[2][16][8];
    __shared__ float2 sfc[2][8][8];
    __shared__ float2 dfc[2][8][8];
    __shared__ float2 tw[64];
    int t = threadIdx.x;
    INIT_TW(tw, t);
    size_t bod0 = (size_t)blockIdx.x * 2;
    for (int i = t; i < 256; i += 128) ((float2*)in2)[i] = Et[bod0*128 + i];
    __syncthreads();
    if (t < 112){
        int l = t / 56, r = t % 56, k = (r >> 3) + 1, kw = r & 7;
        float2 a = in2[l][k][kw], bv = in2[l][16-k][kw];
        sfc[l][k][kw] = make_float2(a.x + bv.x, a.y + bv.y);
        dfc[l][k][kw] = make_float2(a.x - bv.x, a.y - bv.y);
    }
    __syncthreads();
    int l = t >> 6, tt = t & 63, hb = tt >> 3, kw = tt & 7;
    float2 a0  = in2[l][0][kw];
    float2 am8 = in2[l][8][kw];
    size_t obase = (bod0 + l)*512 + kw;                    // + h*8
    for (int hv = hb; hv <= 32; hv += 8){
        if (hv == 0){
            float2 x = make_float2(a0.x + am8.x, a0.y + am8.y);
#pragma unroll
            for (int k = 1; k < 8; k++){ float2 s = sfc[l][k][kw]; x.x += s.x; x.y += s.y; }
            F[obase] = x;
        } else if (hv == 32){
            float2 x = make_float2(a0.x + am8.x, a0.y + am8.y);
#pragma unroll
            for (int k = 1; k < 8; k++){
                float2 s = sfc[l][k][kw];
                if (k & 1){ x.x -= s.x; x.y -= s.y; } else { x.x += s.x; x.y += s.y; }
            }
            F[obase + 32*8] = x;
        } else {
            float2 c8 = tw[(8*hv) & 63];
            float2 U = make_float2(a0.x + am8.x*c8.x, a0.y + am8.y*c8.x);
            float2 W = make_float2(-am8.x*c8.y, -am8.y*c8.y);
            int idx = 0;
#pragma unroll
            for (int k = 1; k < 8; k++){
                idx = (idx + hv) & 63;
                float2 cs = tw[idx];
                float2 s  = sfc[l][k][kw];
                float2 dd = dfc[l][k][kw];
                U.x += s.x*cs.x;  U.y += s.y*cs.x;
                W.x += dd.x*cs.y; W.y += dd.y*cs.y;
            }
            F[obase + (size_t)hv*8]      = make_float2(U.x - W.y, U.y + W.x);
            F[obase + (size_t)(64-hv)*8] = make_float2(U.x + W.y, U.y - W.x);
        }
    }
}

// ==== fused: inv-w + 32x32 pointwise + gelu + NEXT layer forward w-DFT ====
__global__ __launch_bounds__(256) void k_layer(const float2* __restrict__ F,
        const float* __restrict__ xin, const float* __restrict__ wpw,
        const float* __restrict__ bpw, float* __restrict__ xout,
        float2* __restrict__ Anext){
    __shared__ __align__(16) float xs[32][66];
    __shared__ __align__(16) float xs2[32][66];
    __shared__ float2 fs[32][9];
    __shared__ __align__(16) ull wdp[32][32];
    __shared__ float bsm[32];
    __shared__ float2 tw[64];
    __shared__ ull twcc[32][8];
    __shared__ ull twss[32][8];
    int t = threadIdx.x;                      // 256
    INIT_TW(tw, t);
    INIT_TWPK(twcc, twss, t);
    int b = blockIdx.x >> 12, dh = blockIdx.x & 4095;
    { int c = t >> 3, o4 = (t & 7)*4;
#pragma unroll
      for (int j = 0; j < 4; j++){ float wv = wpw[c*32 + o4 + j]; wdp[c][o4+j] = pack2(wv, wv); } }
    if (t < 32) bsm[t] = bpw[t];
    const float* xb = xin + (size_t)b*32*SS + (size_t)dh*64;
    for (int i = t; i < 2048; i += 256){ int c = i >> 6, wd = i & 63; xs[c][wd] = xb[(size_t)c*SS + wd]; }
    const float2* fb = F + ((size_t)b*32*4096 + dh)*8;
    { int o = t >> 3, k = t & 7; fs[o][k] = fb[(size_t)o*32768 + k]; }
    __syncthreads();

    int w2 = (t & 31)*2, ob = (t >> 5)*4;
    float2 c0r[7], c1r[7];
#pragma unroll
    for (int k = 1; k < 8; k++){ int t0 = (k*w2) & 63; c0r[k-1] = tw[t0]; c1r[k-1] = tw[(t0+k) & 63]; }
    ull acc2[4];
#pragma unroll
    for (int oi = 0; oi < 4; oi++){ float bv = bsm[ob+oi]; acc2[oi] = pack2(bv, bv); }
#pragma unroll
    for (int c = 0; c < 32; c++){
        ull xv2 = *(const ull*)&xs[c][w2];
        ulonglong2 wA = *(const ulonglong2*)&wdp[c][ob];
        ulonglong2 wB = *(const ulonglong2*)&wdp[c][ob+2];
        fma2(acc2[0], xv2, wA.x);
        fma2(acc2[1], xv2, wA.y);
        fma2(acc2[2], xv2, wB.x);
        fma2(acc2[3], xv2, wB.y);
    }
    float* orow = xout + (size_t)b*32*SS + (size_t)dh*64;
#pragma unroll
    for (int oi = 0; oi < 4; oi++){
        int o = ob + oi;
        float2 f0 = fs[o][0];
        float i0 = f0.x, i1 = f0.x;
#pragma unroll
        for (int k = 1; k < 8; k++){
            float2 fk = fs[o][k];
            float2 ca = c0r[k-1], cb = c1r[k-1];
            i0 += 2.0f*(fk.x*ca.x - fk.y*ca.y);
            i1 += 2.0f*(fk.x*cb.x - fk.y*cb.y);
        }
        float2 av = unpack2(acc2[oi]);
        float v0 = gelu_f(av.x + i0), v1 = gelu_f(av.y + i1);
        *(float2*)&xs2[o][w2]              = make_float2(v0, v1);
        *(float2*)&orow[(size_t)o*SS + w2] = make_float2(v0, v1);
    }
    __syncthreads();
    { int c = t >> 3, k = t & 7;
      ull re2 = 0ULL, im2 = 0ULL;
#pragma unroll
      for (int i = 0; i < 32; i++){
          ull v2 = *(const ull*)&xs2[c][2*i];
          fma2(re2, v2, twcc[i][k]);
          fma2(im2, v2, twss[i][k]);
      }
      float2 r = unpack2(re2), q = unpack2(im2);
      Anext[((size_t)(b*32 + c)*4096 + dh)*8 + k] = make_float2(r.x + r.y, q.x + q.y);
    }
}

// ==== final layer: inv-w + pointwise (no gelu) + fc1 + gelu + fc2 -> tau ====
__global__ __launch_bounds__(256) void k_final(const float2* __restrict__ F,
        const float* __restrict__ xin, const float* __restrict__ wpw,
        const float* __restrict__ bpw,
        const float* __restrict__ w1, const float* __restrict__ b1,
        const float* __restrict__ w2, const float* __restrict__ b2,
        float* __restrict__ tau){
    __shared__ __align__(16) float xs[32][66];
    __shared__ __align__(16) float xs2[32][66];
    __shared__ float2 fs[32][9];
    __shared__ __align__(16) ull wdp[32][32];
    __shared__ float bsm[32];
    __shared__ float2 tw[64];
    __shared__ __align__(16) float w1s[32][128];
    __shared__ float b1s[128];
    __shared__ ull w2p[64][6];
    __shared__ float b2s[8];
    int t = threadIdx.x;                      // 256
    INIT_TW(tw, t);
    int b = blockIdx.x >> 12, dh = blockIdx.x & 4095;
    { int c = t >> 3, o4 = (t & 7)*4;
#pragma unroll
      for (int j = 0; j < 4; j++){ float wv = wpw[c*32 + o4 + j]; wdp[c][o4+j] = pack2(wv, wv); } }
    if (t < 32) bsm[t] = bpw[t];
    for (int i = t; i < 4096; i += 256) w1s[i >> 7][i & 127] = w1[i];
    if (t < 128) b1s[t] = b1[t];
    for (int i = t; i < 384; i += 256){ int hp = i / 6, j = i - hp*6;
        w2p[hp][j] = pack2(w2[(2*hp)*6 + j], w2[(2*hp+1)*6 + j]); }
    if (t < 6) b2s[t] = b2[t];
    const float* xb = xin + (size_t)b*32*SS + (size_t)dh*64;
    for (int i = t; i < 2048; i += 256){ int c = i >> 6, wd = i & 63; xs[c][wd] = xb[(size_t)c*SS + wd]; }
    const float2* fb = F + ((size_t)b*32*4096 + dh)*8;
    { int o = t >> 3, k = t & 7; fs[o][k] = fb[(size_t)o*32768 + k]; }
    __syncthreads();

    {
        int w2_ = (t & 31)*2, ob = (t >> 5)*4;
        float2 c0r[7], c1r[7];
#pragma unroll
        for (int k = 1; k < 8; k++){ int t0 = (k*w2_) & 63; c0r[k-1] = tw[t0]; c1r[k-1] = tw[(t0+k) & 63]; }
        ull acc2[4];
#pragma unroll
        for (int oi = 0; oi < 4; oi++){ float bv = bsm[ob+oi]; acc2[oi] = pack2(bv, bv); }
#pragma unroll
        for (int c = 0; c < 32; c++){
            ull xv2 = *(const ull*)&xs[c][w2_];
            ulonglong2 wA = *(const ulonglong2*)&wdp[c][ob];
            ulonglong2 wB = *(const ulonglong2*)&wdp[c][ob+2];
            fma2(acc2[0], xv2, wA.x);
            fma2(acc2[1], xv2, wA.y);
            fma2(acc2[2], xv2, wB.x);
            fma2(acc2[3], xv2, wB.y);
        }
#pragma unroll
        for (int oi = 0; oi < 4; oi++){
            int o = ob + oi;
            float2 f0 = fs[o][0];
            float i0 = f0.x, i1 = f0.x;
#pragma unroll
            for (int k = 1; k < 8; k++){
                float2 fk = fs[o][k];
                float2 ca = c0r[k-1], cb = c1r[k-1];
                i0 += 2.0f*(fk.x*ca.x - fk.y*ca.y);
                i1 += 2.0f*(fk.x*cb.x - fk.y*cb.y);
            }
            float2 av = unpack2(acc2[oi]);
            *(float2*)&xs2[o][w2_] = make_float2(av.x + i0, av.y + i1);
        }
    }
    __syncthreads();

    {
        int q = t & 3, wd = t >> 2;
        ull g[16];
#pragma unroll
        for (int hq = 0; hq < 8; hq++){
            int H = 16*hq + 4*q;
            g[2*hq]   = pack2(b1s[H],   b1s[H+1]);
            g[2*hq+1] = pack2(b1s[H+2], b1s[H+3]);
        }
#pragma unroll 4
        for (int c = 0; c < 32; c++){
            float xv = xs2[c][wd];
            ull xvd = pack2(xv, xv);
#pragma unroll
            for (int hq = 0; hq < 8; hq++){
                ulonglong2 wp = *(const ulonglong2*)&w1s[c][16*hq + 4*q];
                fma2(g[2*hq],   xvd, wp.x);
                fma2(g[2*hq+1], xvd, wp.y);
            }
        }
        ull a2[6];
#pragma unroll
        for (int j = 0; j < 6; j++) a2[j] = 0ULL;
#pragma unroll
        for (int hq = 0; hq < 8; hq++){
            float2 g01 = unpack2(g[2*hq]), g23 = unpack2(g[2*hq+1]);
            ull gp0 = pack2(gelu_f(g01.x), gelu_f(g01.y));
            ull gp1 = pack2(gelu_f(g23.x), gelu_f(g23.y));
            int hp = 8*hq + 2*q;
#pragma unroll
            for (int j = 0; j < 6; j++){
                fma2(a2[j], gp0, w2p[hp][j]);
                fma2(a2[j], gp1, w2p[hp+1][j]);
            }
        }
        float* tb = tau + (size_t)b*6*SS + (size_t)dh*64 + wd;
#pragma unroll
        for (int j = 0; j < 6; j++){
            float2 av = unpack2(a2[j]);
            float aj = av.x + av.y;
            aj += __shfl_xor_sync(0xffffffffu, aj, 1);
            aj += __shfl_xor_sync(0xffffffffu, aj, 2);
            if (q == 0) tb[(size_t)j*SS] = aj + b2s[j];
        }
    }
}

// ============ NS hard core stencil + 0.001*tau[:3] ============
__global__ void k_stencil(const float* __restrict__ u, const float* __restrict__ tau,
                          float* __restrict__ du){
    int idx = blockIdx.x * 256 + threadIdx.x;
    int s  = idx & (SS - 1);
    int bi = idx >> 18;
    int b  = bi / 3;
    int i  = bi - b*3;
    int w = s & 63, h = (s >> 6) & 63, d = s >> 12;
    const float* ui = u + (size_t)bi * SS;
    float c0 = ui[s];
    int wp = (w + 1) & 63, wm = (w + 63) & 63;
    int hp = (h + 1) & 63, hm = (h + 63) & 63;
    int dp = (d + 1) & 63, dm = (d + 63) & 63;
    float uwp = ui[(d << 12) + (h << 6) + wp], uwm = ui[(d << 12) + (h << 6) + wm];
    float uhp = ui[(d << 12) + (hp << 6) + w], uhm = ui[(d << 12) + (hm << 6) + w];
    float udp = ui[(dp << 12) + (h << 6) + w], udm = ui[(dm << 12) + (h << 6) + w];
    const float inv2dx = (float)(16.0 / 3.14159265358979323846);
    const float invdx2 = (float)(1024.0 / (3.14159265358979323846*3.14159265358979323846));
    float v0 = u[((size_t)b*3 + 0)*SS + s];
    float v1 = u[((size_t)b*3 + 1)*SS + s];
    float v2 = u[((size_t)b*3 + 2)*SS + s];
    float conv = -(v0*(udp - udm) + v1*(uhp - uhm) + v2*(uwp - uwm)) * inv2dx;
    float lap  = (udp + udm + uhp + uhm + uwp + uwm - 6.0f*c0) * invdx2;
    float tv = tau[((size_t)b*6 + i)*SS + s];
    du[idx] = conv + 0.000185f*lap + 0.001f*tv;
}

// ============ launch ============
extern "C" void kernel_launch(void* const* d_in, const int* in_sizes, int n_in,
                              void* d_out, int out_size){
    const float* u      = (const float*)d_in[0];
    const float* fc0_w  = (const float*)d_in[1];
    const float* fc0_b  = (const float*)d_in[2];
    const float* spec_w = (const float*)d_in[3];
    const float* w_pw   = (const float*)d_in[4];
    const float* b_pw   = (const float*)d_in[5];
    const float* fc1_w  = (const float*)d_in[6];
    const float* fc1_b  = (const float*)d_in[7];
    const float* fc2_w  = (const float*)d_in[8];
    const float* fc2_b  = (const float*)d_in[9];

    float* du  = (float*)d_out;
    float* tau = du + (size_t)BB*3*SS;

    float *x0; float2 *A, *Bt, *Ct, *Dt, *Et;
    cudaGetSymbolAddress((void**)&x0, g_x0);
    cudaGetSymbolAddress((void**)&A,  g_A);
    cudaGetSymbolAddress((void**)&Bt, g_B);
    cudaGetSymbolAddress((void**)&Ct, g_C);
    cudaGetSymbolAddress((void**)&Dt, g_D);
    cudaGetSymbolAddress((void**)&Et, g_E);

    k_fc0_fw<<<16384, 256>>>(u, fc0_w, fc0_b, x0, A);

    for (int l = 0; l < 4; l++){
        k_fwd_h<<<4096, 128>>>(A, Bt);
        k_fwd_d<<<1024, 128>>>(Bt, Ct);
        k_mix  <<<256, 128>>>(Ct, spec_w + (size_t)l*4*32*32*512*2, Dt);
        k_inv_d<<<1024, 128>>>(Dt, Et);
        k_inv_h<<<4096, 128>>>(Et, A);
        if (l < 3){
            k_layer<<<16384, 256>>>(A, x0, w_pw + (size_t)l*1024, b_pw + (size_t)l*32,
                                    x0, A);
        } else {
            k_final<<<16384, 256>>>(A, x0, w_pw + (size_t)l*1024, b_pw + (size_t)l*32,
                                    fc1_w, fc1_b, fc2_w, fc2_b, tau);
        }
    }

    k_stencil<<<12288, 256>>>(u, tau, du);
}